// round 10
// baseline (speedup 1.0000x reference)
#include <cuda_runtime.h>
#include <cuda_fp16.h>
#include <cstdint>
#include <cstddef>

#define DD 4096
#define MM 8192

// Scratch: Hadamard-rotated fp16 W [N,K]; fp16 x [M,K].
__device__ __align__(256) __half g_Wh[(size_t)DD * DD];
__device__ __align__(256) __half g_Xh[(size_t)MM * DD];

// ---------------------------------------------------------------------------
// Kernel 1 (fused prep):
//   blocks [0, 4096):     row-wise WHT of W (reg+shuffle+smem), /64, fp16
//   blocks [4096, 8192):  convert x to fp16
// (xH)W^T == x(WH)^T since H is symmetric.
// ---------------------------------------------------------------------------
__global__ void prep_kernel(const float* __restrict__ W,
                            const float4* __restrict__ x) {
    if (blockIdx.x < DD) {
        __shared__ float sh[DD];
        const int t = threadIdx.x;          // 512 threads
        const int lane = t & 31;
        const int w = t >> 5;
        const float4* src = (const float4*)(W + (size_t)blockIdx.x * DD) + t * 2;
        float v[8];
        {
            float4 u0 = src[0], u1 = src[1];
            v[0] = u0.x; v[1] = u0.y; v[2] = u0.z; v[3] = u0.w;
            v[4] = u1.x; v[5] = u1.y; v[6] = u1.z; v[7] = u1.w;
        }
#pragma unroll
        for (int len = 1; len <= 4; len <<= 1) {
#pragma unroll
            for (int e = 0; e < 8; ++e) {
                if ((e & len) == 0) {
                    float a = v[e], b = v[e | len];
                    v[e] = a + b;
                    v[e | len] = a - b;
                }
            }
        }
#pragma unroll
        for (int m = 1; m <= 16; m <<= 1) {
#pragma unroll
            for (int e = 0; e < 8; ++e) {
                float r = __shfl_xor_sync(0xffffffffu, v[e], m);
                v[e] = (lane & m) ? (r - v[e]) : (v[e] + r);
            }
        }
#pragma unroll
        for (int mw = 1; mw <= 8; mw <<= 1) {
            __syncthreads();
#pragma unroll
            for (int e = 0; e < 8; ++e) sh[t * 8 + e] = v[e];
            __syncthreads();
            const int p = (t ^ (mw * 32)) * 8;
#pragma unroll
            for (int e = 0; e < 8; ++e) {
                float r = sh[p + e];
                v[e] = (w & mw) ? (r - v[e]) : (v[e] + r);
            }
        }
        __half2 h[4];
#pragma unroll
        for (int e = 0; e < 4; ++e)
            h[e] = __floats2half2_rn(v[2 * e] * 0.015625f, v[2 * e + 1] * 0.015625f);
        uint4 o;
        o.x = *(uint32_t*)&h[0]; o.y = *(uint32_t*)&h[1];
        o.z = *(uint32_t*)&h[2]; o.w = *(uint32_t*)&h[3];
        *((uint4*)(g_Wh + (size_t)blockIdx.x * DD) + t) = o;
    } else {
        const size_t base = ((size_t)(blockIdx.x - DD) * blockDim.x + threadIdx.x) * 2;
#pragma unroll
        for (int u = 0; u < 2; ++u) {
            const size_t idx = base + u;
            float4 v0 = x[2 * idx];
            float4 v1 = x[2 * idx + 1];
            __half2 h0 = __floats2half2_rn(v0.x, v0.y);
            __half2 h1 = __floats2half2_rn(v0.z, v0.w);
            __half2 h2 = __floats2half2_rn(v1.x, v1.y);
            __half2 h3 = __floats2half2_rn(v1.z, v1.w);
            uint4 o;
            o.x = *(uint32_t*)&h0; o.y = *(uint32_t*)&h1;
            o.z = *(uint32_t*)&h2; o.w = *(uint32_t*)&h3;
            ((uint4*)g_Xh)[idx] = o;
        }
    }
}

// ---------------------------------------------------------------------------
// Kernel 2: persistent fp16 mma.sync GEMM  out = Xh @ Wh^T + bias
// CTA 128x128, 4 warps (2x2), warp tile 64x64, TKH=64, 3-stage cp.async,
// XOR-swizzled smem, 2 CTAs/SM, grid=296 persistent: the 3-stage pipeline
// rotates continuously ACROSS tiles (next tile's loads overlap this tile's
// tail + epilogue; pipeline never drains between tiles).
// ---------------------------------------------------------------------------
constexpr int TM = 128;
constexpr int TN = 128;
constexpr int TKH = 64;                      // halves per K-tile (128 B)
constexpr int NKT = DD / TKH;                // 64
constexpr int A_BYTES = TM * 128;            // 16384
constexpr int B_BYTES = TN * 128;            // 16384
constexpr int STAGE_BYTES = A_BYTES + B_BYTES;          // 32768
constexpr int SMEM_TOTAL = 3 * STAGE_BYTES;             // 98304
constexpr int NTHREADS = 128;
constexpr int NTILES = (MM / TM) * (DD / TN);           // 2048
constexpr int GRID = 296;                               // 148 SMs x 2

__device__ __forceinline__ uint32_t smem_u32(const void* p) {
    return (uint32_t)__cvta_generic_to_shared(p);
}
__device__ __forceinline__ void cp16(uint32_t dst, const void* src) {
    asm volatile("cp.async.cg.shared.global [%0], [%1], 16;\n" :: "r"(dst), "l"(src));
}
__device__ __forceinline__ void ldsm4(uint32_t* r, uint32_t addr) {
    asm volatile("ldmatrix.sync.aligned.m8n8.x4.shared.b16 {%0,%1,%2,%3}, [%4];"
                 : "=r"(r[0]), "=r"(r[1]), "=r"(r[2]), "=r"(r[3]) : "r"(addr));
}
__device__ __forceinline__ void mma_f16(float* c, const uint32_t* a, const uint32_t* b) {
    asm volatile(
        "mma.sync.aligned.m16n8k16.row.col.f32.f16.f16.f32 "
        "{%0,%1,%2,%3}, {%4,%5,%6,%7}, {%8,%9}, {%0,%1,%2,%3};"
        : "+f"(c[0]), "+f"(c[1]), "+f"(c[2]), "+f"(c[3])
        : "r"(a[0]), "r"(a[1]), "r"(a[2]), "r"(a[3]),
          "r"(b[0]), "r"(b[1]));
}

// swizzled byte offset inside a 128B-wide tile
__device__ __forceinline__ uint32_t sw_off(int row, int chunk) {
    return (uint32_t)(row * 128 + ((chunk ^ (row & 7)) << 4));
}

// tile id -> (m0, n0) with G=16 M-group swizzle for L2 locality
__device__ __forceinline__ void tile_mn(int pid, int& m0, int& n0) {
    constexpr int PN = DD / TN;           // 32
    constexpr int G = 16;
    const int grp = pid / (G * PN);
    const int pm = grp * G + (pid % G);
    const int pn = (pid % (G * PN)) / G;
    m0 = pm * TM;
    n0 = pn * TN;
}

__device__ __forceinline__ void issue_stage(int m0, int n0, int kt, int slot,
                                            uint32_t sbase, int tid) {
    const uint32_t stA = sbase + (uint32_t)(slot * STAGE_BYTES);
    const uint32_t stB = stA + A_BYTES;
    const __half* gA = g_Xh + (size_t)m0 * DD + kt * TKH;
    const __half* gB = g_Wh + (size_t)n0 * DD + kt * TKH;
#pragma unroll
    for (int i = 0; i < 8; ++i) {            // A: 1024 16B chunks
        const int idx = tid + i * NTHREADS;
        const int row = idx >> 3;
        const int c = idx & 7;
        cp16(stA + sw_off(row, c), gA + (size_t)row * DD + c * 8);
    }
#pragma unroll
    for (int i = 0; i < 8; ++i) {            // B: 1024 16B chunks
        const int idx = tid + i * NTHREADS;
        const int row = idx >> 3;
        const int c = idx & 7;
        cp16(stB + sw_off(row, c), gB + (size_t)row * DD + c * 8);
    }
    asm volatile("cp.async.commit_group;\n" ::: "memory");
}

__global__ void __launch_bounds__(NTHREADS, 2)
gemm_f16_kernel(const float* __restrict__ bias, float* __restrict__ out) {
    extern __shared__ char smem[];
    const uint32_t sbase = smem_u32(smem);
    const int tid = threadIdx.x;
    const int wid = tid >> 5;
    const int lane = tid & 31;
    const int g = lane >> 2;              // accumulator row within 8
    const int nc2 = (lane & 3) * 2;       // accumulator n-col base
    const int wm = wid & 1;               // 2 warps along M (64 rows each)
    const int wn = wid >> 1;              // 2 warps along N (64 cols each)

    // per-lane ldmatrix row/chunk components
    const int a_row = lane & 15;
    const int a_cofs = lane >> 4;                       // 0/1
    const int b_row = ((lane >> 4) << 3) + (lane & 7);
    const int b_cofs = (lane >> 3) & 1;                 // 0/1

    int t = blockIdx.x;
    if (t >= NTILES) return;
    int m0, n0;
    tile_mn(t, m0, n0);

    // prologue: 2 stages of the first tile
    issue_stage(m0, n0, 0, 0, sbase, tid);
    issue_stage(m0, n0, 1, 1, sbase, tid);
    int slot_cons = 0;      // slot consumed this iteration
    int inflight = 2;       // committed cp.async groups not yet retired

    while (true) {
        const int tn = t + GRID;
        const bool have_next = (tn < NTILES);
        int nm0 = 0, nn0 = 0;
        if (have_next) tile_mn(tn, nm0, nn0);

        float acc[4][8][4];
#pragma unroll
        for (int mi = 0; mi < 4; ++mi)
#pragma unroll
            for (int ni = 0; ni < 8; ++ni)
#pragma unroll
                for (int v = 0; v < 4; ++v) acc[mi][ni][v] = 0.0f;

        for (int kt = 0; kt < NKT; ++kt) {
            if (inflight >= 2) {
                asm volatile("cp.async.wait_group 1;\n" ::: "memory");
            } else {
                asm volatile("cp.async.wait_group 0;\n" ::: "memory");
            }
            __syncthreads();

            // fill 2 stages ahead (may belong to the next tile)
            const int gk = kt + 2;
            const int slot_fill = (slot_cons + 2) % 3;
            bool filled = false;
            if (gk < NKT) {
                issue_stage(m0, n0, gk, slot_fill, sbase, tid);
                filled = true;
            } else if (have_next) {
                issue_stage(nm0, nn0, gk - NKT, slot_fill, sbase, tid);
                filled = true;
            }
            inflight += (filled ? 1 : 0) - 1;

            const uint32_t sA = sbase + (uint32_t)(slot_cons * STAGE_BYTES);
            const uint32_t sB = sA + A_BYTES;

            // double-buffered fragments: load step s+1 while computing step s
            uint32_t a[2][4][4];
            uint32_t bf[2][4][4];
#pragma unroll
            for (int mi = 0; mi < 4; ++mi)
                ldsm4(a[0][mi], sA + sw_off(wm * 64 + mi * 16 + a_row, a_cofs));
#pragma unroll
            for (int j = 0; j < 4; ++j)
                ldsm4(bf[0][j], sB + sw_off(wn * 64 + j * 16 + b_row, b_cofs));

#pragma unroll
            for (int s = 0; s < TKH / 16; ++s) {   // 4 k16 steps
                const int cur = s & 1;
                const int nxt = cur ^ 1;
                if (s < TKH / 16 - 1) {
#pragma unroll
                    for (int mi = 0; mi < 4; ++mi)
                        ldsm4(a[nxt][mi],
                              sA + sw_off(wm * 64 + mi * 16 + a_row, 2 * (s + 1) + a_cofs));
#pragma unroll
                    for (int j = 0; j < 4; ++j)
                        ldsm4(bf[nxt][j],
                              sB + sw_off(wn * 64 + j * 16 + b_row, 2 * (s + 1) + b_cofs));
                }
#pragma unroll
                for (int mi = 0; mi < 4; ++mi)
#pragma unroll
                    for (int ni = 0; ni < 8; ++ni)
                        mma_f16(acc[mi][ni], a[cur][mi], &bf[cur][ni >> 1][(ni & 1) * 2]);
            }
            slot_cons = (slot_cons + 1) % 3;
        }

        // epilogue (next tile's first stages already in flight)
#pragma unroll
        for (int mi = 0; mi < 4; ++mi) {
            const int m = m0 + wm * 64 + mi * 16 + g;
#pragma unroll
            for (int ni = 0; ni < 8; ++ni) {
                const int n = n0 + wn * 64 + ni * 8 + nc2;
                const float2 bb = *(const float2*)(bias + n);
                float2 o0, o1;
                o0.x = acc[mi][ni][0] + bb.x;
                o0.y = acc[mi][ni][1] + bb.y;
                o1.x = acc[mi][ni][2] + bb.x;
                o1.y = acc[mi][ni][3] + bb.y;
                *(float2*)(out + (size_t)m * DD + n) = o0;
                *(float2*)(out + (size_t)(m + 8) * DD + n) = o1;
            }
        }

        if (!have_next) break;
        t = tn;
        m0 = nm0;
        n0 = nn0;
    }
}

// ---------------------------------------------------------------------------
extern "C" void kernel_launch(void* const* d_in, const int* in_sizes, int n_in,
                              void* d_out, int out_size) {
    const float* x = (const float*)d_in[0];   // [4,2048,4096] -> M=8192
    const float* W = (const float*)d_in[1];   // [4096,4096]
    const float* b = (const float*)d_in[2];   // [4096]
    float* out = (float*)d_out;

    cudaFuncSetAttribute(gemm_f16_kernel,
                         cudaFuncAttributeMaxDynamicSharedMemorySize, SMEM_TOTAL);

    prep_kernel<<<2 * DD, 512>>>(W, (const float4*)x);
    gemm_f16_kernel<<<GRID, NTHREADS, SMEM_TOTAL>>>(b, out);
}